// round 12
// baseline (speedup 1.0000x reference)
#include <cuda_runtime.h>
#include <cuda_fp16.h>
#include <cuda_bf16.h>
#include <cstddef>
#include <cstdint>

// ---------------------------------------------------------------------------
// GCN: 5 GraphConv + 3 edge-weighted aggregations. CSR-gather + tensor cores.
// R12 = R11 (297.0us) + degree-sorted node permutation for all gather kernels:
//   counting-sort nodes by in-degree so each warp processes near-equal-degree
//   nodes -> removes intra-warp edge-loop divergence (E[max deg in warp] ~1.7x
//   mean). Gather bodies otherwise frozen; outputs still indexed by node id
//   (bitwise-identical results).
// ---------------------------------------------------------------------------

#define NN 50000
#define NE 800000

__device__ int   g_ideg[NN];
__device__ int   g_odeg[NN];
__device__ int   g_cnt[NN];
__device__ int   g_off[NN + 1];
__device__ __align__(16) int2  g_edge[NE];   // {src, __float_as_int(efet)}
__device__ float g_norm_out[NN];
__device__ float g_norm_in[NN];
__device__ int   g_hist[256];
__device__ int   g_hoff[257];
__device__ int   g_hcnt[256];
__device__ int   g_perm[NN];
__device__ __align__(16) float g_bufA[(size_t)NN * 256];
__device__ __align__(16) float g_bufB[(size_t)NN * 256];
__device__ __align__(16) float g_bufC[(size_t)NN * 256];
// transposed fp16 weights: W2t[128][256], W3t[64][128], W4t[32][64]
__device__ __align__(16) __half g_w2t[128 * 256];
__device__ __align__(16) __half g_w3t[64 * 128];
__device__ __align__(16) __half g_w4t[32 * 64];

// ---- degrees / norms -------------------------------------------------------

__global__ void deg_k(const int* __restrict__ src, const int* __restrict__ dst) {
    int e = blockIdx.x * blockDim.x + threadIdx.x;
    if (e < NE) {
        atomicAdd(&g_odeg[src[e]], 1);
        atomicAdd(&g_ideg[dst[e]], 1);
    }
}

__global__ void norm_k() {
    int i = blockIdx.x * blockDim.x + threadIdx.x;
    if (i < NN) {
        g_norm_out[i] = rsqrtf(fmaxf((float)g_odeg[i], 1.0f));
        g_norm_in[i]  = rsqrtf(fmaxf((float)g_ideg[i], 1.0f));
    }
}

// ---- exclusive scan of in-degrees -> CSR offsets (single block) ------------

__global__ void scan_k() {
    __shared__ int sh[1024];
    const int t = threadIdx.x;
    const int CH = (NN + 1023) / 1024;
    int beg = t * CH, end = min(beg + CH, NN);
    int s = 0;
    for (int i = beg; i < end; i++) s += g_ideg[i];
    sh[t] = s;
    __syncthreads();
    for (int ofs = 1; ofs < 1024; ofs <<= 1) {
        int v = (t >= ofs) ? sh[t - ofs] : 0;
        __syncthreads();
        sh[t] += v;
        __syncthreads();
    }
    int run = (t == 0) ? 0 : sh[t - 1];
    for (int i = beg; i < end; i++) { g_off[i] = run; run += g_ideg[i]; }
    if (end == NN) g_off[NN] = run;
}

__global__ void fill_k(const int* __restrict__ src, const int* __restrict__ dst,
                       const float* __restrict__ efet) {
    int e = blockIdx.x * blockDim.x + threadIdx.x;
    if (e < NE) {
        int d = dst[e];
        int pos = g_off[d] + atomicAdd(&g_cnt[d], 1);
        g_edge[pos] = make_int2(src[e], __float_as_int(efet[e]));
    }
}

// ---- degree-sorted permutation (counting sort, 256 bins) -------------------

__global__ void hist_k() {
    int i = blockIdx.x * blockDim.x + threadIdx.x;
    if (i < NN) atomicAdd(&g_hist[min(g_ideg[i], 255)], 1);
}

__global__ void hscan_k() {     // 256 threads, 1 block
    __shared__ int sh[256];
    int t = threadIdx.x;
    sh[t] = g_hist[t];
    __syncthreads();
    for (int o = 1; o < 256; o <<= 1) {
        int v = (t >= o) ? sh[t - o] : 0;
        __syncthreads();
        sh[t] += v;
        __syncthreads();
    }
    g_hoff[t + 1] = sh[t];
    if (t == 0) g_hoff[0] = 0;
}

__global__ void permfill_k() {
    int i = blockIdx.x * blockDim.x + threadIdx.x;
    if (i < NN) {
        int d = min(g_ideg[i], 255);
        int pos = g_hoff[d] + atomicAdd(&g_hcnt[d], 1);
        g_perm[pos] = i;
    }
}

// ---- W -> Wt fp16 transpose (tiny) -----------------------------------------

template <int K, int N>
__global__ void wcvt_k(const float* __restrict__ W, __half* __restrict__ Wt) {
    int i = blockIdx.x * blockDim.x + threadIdx.x;
    if (i < K * N) {
        int k = i / N, n = i % N;
        Wt[(size_t)n * K + k] = __float2half(W[i]);
    }
}

// ---- fp32 gather (16 pre-agg, 4 final), degree-sorted ----------------------
// WMODE: 0 = w=1, 1 = w=efet, 2 = w=out_norm[src]

template <int F, int WMODE, bool EPI, bool RELU>
__global__ void gather_k(const float* __restrict__ m,
                         const float* __restrict__ b,
                         float* __restrict__ out) {
    constexpr int NT = F / 4;
    constexpr int NPB = 256 / NT;
    int t = threadIdx.x;
    int idx = blockIdx.x * NPB + t / NT;
    int c = t % NT;
    if (idx >= NN) return;
    int node = g_perm[idx];
    int beg = g_off[node], end = g_off[node + 1];

    float4 acc = make_float4(0.f, 0.f, 0.f, 0.f);
    for (int e = beg; e < end; e++) {
        int2 sc = g_edge[e];
        int s = sc.x;
        float w = 1.0f;
        if (WMODE == 1) w = __int_as_float(sc.y);
        if (WMODE == 2) w = g_norm_out[s];
        float4 v = *(const float4*)(m + (size_t)s * F + c * 4);
        acc.x += v.x * w; acc.y += v.y * w; acc.z += v.z * w; acc.w += v.w * w;
    }
    if (EPI) {
        float ni = g_norm_in[node];
        acc.x = acc.x * ni + b[c * 4 + 0];
        acc.y = acc.y * ni + b[c * 4 + 1];
        acc.z = acc.z * ni + b[c * 4 + 2];
        acc.w = acc.w * ni + b[c * 4 + 3];
    }
    if (RELU) {
        acc.x = fmaxf(acc.x, 0.f); acc.y = fmaxf(acc.y, 0.f);
        acc.z = fmaxf(acc.z, 0.f); acc.w = fmaxf(acc.w, 0.f);
    }
    *(float4*)(out + (size_t)node * F + c * 4) = acc;
}

// ---- fp16-input gather, degree-sorted ---------------------------------------
// 8 halves per thread, fp32 accumulation, x2 edge unroll (frozen config).
// ONORM: multiply final result by out_norm[node].  OH: fp16 output.

__device__ __forceinline__ void acc8(float* a, uint4 r, float w) {
    float2 f;
    f = __half22float2(*(const __half2*)&r.x); a[0] += f.x * w; a[1] += f.y * w;
    f = __half22float2(*(const __half2*)&r.y); a[2] += f.x * w; a[3] += f.y * w;
    f = __half22float2(*(const __half2*)&r.z); a[4] += f.x * w; a[5] += f.y * w;
    f = __half22float2(*(const __half2*)&r.w); a[6] += f.x * w; a[7] += f.y * w;
}

template <int F, int WMODE, bool EPI, bool RELU, bool ONORM, bool OH>
__global__ void gather_h_k(const __half* __restrict__ m,
                           const float* __restrict__ b,
                           void* __restrict__ outp) {
    constexpr int NT = F / 8;
    constexpr int NPB = 256 / NT;
    int t = threadIdx.x;
    int idx = blockIdx.x * NPB + t / NT;
    int c = t % NT;
    if (idx >= NN) return;
    int node = g_perm[idx];
    int beg = g_off[node], end = g_off[node + 1];

    float acc[8];
#pragma unroll
    for (int i = 0; i < 8; i++) acc[i] = 0.f;

    const uint4* base = (const uint4*)m;
    int e = beg;
    for (; e + 2 <= end; e += 2) {
        int2 sc0 = g_edge[e], sc1 = g_edge[e + 1];
        float w0 = 1.f, w1 = 1.f;
        if (WMODE == 1) { w0 = __int_as_float(sc0.y); w1 = __int_as_float(sc1.y); }
        uint4 r0 = base[(size_t)sc0.x * NT + c];
        uint4 r1 = base[(size_t)sc1.x * NT + c];
        acc8(acc, r0, w0);
        acc8(acc, r1, w1);
    }
    if (e < end) {
        int2 sc = g_edge[e];
        float w = (WMODE == 1) ? __int_as_float(sc.y) : 1.f;
        uint4 r = base[(size_t)sc.x * NT + c];
        acc8(acc, r, w);
    }

    if (EPI) {
        float ni = g_norm_in[node];
#pragma unroll
        for (int i = 0; i < 8; i++) acc[i] = acc[i] * ni + b[c * 8 + i];
    }
    if (RELU) {
#pragma unroll
        for (int i = 0; i < 8; i++) acc[i] = fmaxf(acc[i], 0.f);
    }
    if (ONORM) {
        float no = g_norm_out[node];
#pragma unroll
        for (int i = 0; i < 8; i++) acc[i] *= no;
    }
    if (OH) {
        __half2 h0 = __floats2half2_rn(acc[0], acc[1]);
        __half2 h1 = __floats2half2_rn(acc[2], acc[3]);
        __half2 h2 = __floats2half2_rn(acc[4], acc[5]);
        __half2 h3 = __floats2half2_rn(acc[6], acc[7]);
        uint4 r;
        r.x = *(const unsigned*)&h0; r.y = *(const unsigned*)&h1;
        r.z = *(const unsigned*)&h2; r.w = *(const unsigned*)&h3;
        ((uint4*)outp)[(size_t)node * NT + c] = r;
    } else {
        float* o = (float*)outp + (size_t)node * F + c * 8;
        *(float4*)(o + 0) = make_float4(acc[0], acc[1], acc[2], acc[3]);
        *(float4*)(o + 4) = make_float4(acc[4], acc[5], acc[6], acc[7]);
    }
}

// ---- tensor-core GEMM: D[M,N] = A[M,K] @ W[K,N], fp16 in / fp32 acc --------

template <int K, int N>
__global__ void mma_gemm_k(const __half* __restrict__ A,
                           const __half* __restrict__ Wt,
                           __half* __restrict__ D) {
    constexpr int WN = (N >= 64) ? 64 : N;       // warp n-extent
    constexpr int TN = WN / 8;                   // n8 tiles per warp
    constexpr int WARPS_N = N / WN;
    constexpr int WARPS_M = 8 / WARPS_N;
    constexpr int BM = WARPS_M * 16;
    constexpr int PITCH = K + 8;                 // +16B pad -> bank rotation
    constexpr int KC = K / 16;                   // k16 chunks

    __shared__ __half sA[BM * PITCH];

    const int tid = threadIdx.x;
    const int lane = tid & 31;
    const int wid = tid >> 5;
    const int wm = wid % WARPS_M;
    const int wn = wid / WARPS_M;
    const int blockStart = blockIdx.x * BM;

    for (int i = tid; i < BM * (K / 8); i += 256) {
        int row = i / (K / 8), chunk = i % (K / 8);
        int node = blockStart + row;
        uint4 v = make_uint4(0, 0, 0, 0);
        if (node < NN) v = ((const uint4*)A)[(size_t)node * (K / 8) + chunk];
        *(uint4*)(&sA[row * PITCH + chunk * 8]) = v;
    }
    __syncthreads();

    float acc[TN][4];
#pragma unroll
    for (int t = 0; t < TN; t++)
#pragma unroll
        for (int i = 0; i < 4; i++) acc[t][i] = 0.f;

    const int q = lane >> 3, r = lane & 7;
    const int arow = wm * 16 + r + 8 * (q & 1);
    const int acol0 = 8 * (q >> 1);
    unsigned abase;
    {
        const void* p = &sA[arow * PITCH + acol0];
        asm("{ .reg .u64 t; cvta.to.shared.u64 t, %1; cvt.u32.u64 %0, t; }"
            : "=r"(abase) : "l"(p));
    }

    const __half* wbase = Wt + (size_t)(wn * WN + (lane >> 2)) * K + (lane & 3) * 2;

#pragma unroll
    for (int kc = 0; kc < KC; kc++) {
        unsigned a0, a1, a2, a3;
        asm volatile("ldmatrix.sync.aligned.m8n8.x4.shared.b16 {%0,%1,%2,%3}, [%4];"
                     : "=r"(a0), "=r"(a1), "=r"(a2), "=r"(a3)
                     : "r"(abase + kc * 32));
#pragma unroll
        for (int tn = 0; tn < TN; tn++) {
            unsigned b0 = *(const unsigned*)(wbase + (size_t)tn * 8 * K + kc * 16);
            unsigned b1 = *(const unsigned*)(wbase + (size_t)tn * 8 * K + kc * 16 + 8);
            asm volatile(
                "mma.sync.aligned.m16n8k16.row.col.f32.f16.f16.f32 "
                "{%0,%1,%2,%3}, {%4,%5,%6,%7}, {%8,%9}, {%0,%1,%2,%3};"
                : "+f"(acc[tn][0]), "+f"(acc[tn][1]), "+f"(acc[tn][2]), "+f"(acc[tn][3])
                : "r"(a0), "r"(a1), "r"(a2), "r"(a3), "r"(b0), "r"(b1));
        }
    }

    const int node0 = blockStart + wm * 16 + (lane >> 2);
    const int node1 = node0 + 8;
#pragma unroll
    for (int tn = 0; tn < TN; tn++) {
        int gcol = wn * WN + tn * 8 + (lane & 3) * 2;
        if (node0 < NN) {
            __half2 h = __floats2half2_rn(acc[tn][0], acc[tn][1]);
            *(unsigned*)(D + (size_t)node0 * N + gcol) = *(const unsigned*)&h;
        }
        if (node1 < NN) {
            __half2 h = __floats2half2_rn(acc[tn][2], acc[tn][3]);
            *(unsigned*)(D + (size_t)node1 * N + gcol) = *(const unsigned*)&h;
        }
    }
}

// ---- gemm1: agg16 @ W1 (16x256), fused in_norm+bias+relu, fp16 out ---------

__global__ void gemm1_k(const float* __restrict__ h, const float* __restrict__ W,
                        const float* __restrict__ b, __half* __restrict__ out) {
    __shared__ float sh[64 * 16];
    const int j = threadIdx.x;
    float w[16];
#pragma unroll
    for (int k = 0; k < 16; k++) w[k] = W[k * 256 + j];
    float bj = b[j];
    int nbase = blockIdx.x * 64;
    for (int i = j; i < 64 * 16; i += 256) {
        int node = nbase + i / 16;
        sh[i] = (node < NN) ? h[(size_t)node * 16 + (i % 16)] : 0.f;
    }
    __syncthreads();
#pragma unroll 4
    for (int ln = 0; ln < 64; ln++) {
        int node = nbase + ln;
        if (node >= NN) break;
        float acc = 0.f;
#pragma unroll
        for (int k = 0; k < 16; k++) acc += sh[ln * 16 + k] * w[k];
        acc = acc * g_norm_in[node] + bj;
        out[(size_t)node * 256 + j] = __float2half(fmaxf(acc, 0.f));
    }
}

// ---- gemm5: 32 -> 4 (tiny fp32), thread = node -----------------------------

__global__ void gemm5_k(const float* __restrict__ h, const float* __restrict__ W,
                        float* __restrict__ out) {
    __shared__ float sw[32 * 4];
    if (threadIdx.x < 128) sw[threadIdx.x] = W[threadIdx.x];
    __syncthreads();
    int node = blockIdx.x * 256 + threadIdx.x;
    if (node >= NN) return;
    float no = g_norm_out[node];
    float acc[4] = {0.f, 0.f, 0.f, 0.f};
    const float4* row = (const float4*)(h + (size_t)node * 32);
#pragma unroll
    for (int k4 = 0; k4 < 8; k4++) {
        float4 v = row[k4];
        float vv[4] = {v.x * no, v.y * no, v.z * no, v.w * no};
#pragma unroll
        for (int i = 0; i < 4; i++)
#pragma unroll
            for (int j = 0; j < 4; j++)
                acc[j] += vv[i] * sw[(k4 * 4 + i) * 4 + j];
    }
    *(float4*)(out + (size_t)node * 4) = make_float4(acc[0], acc[1], acc[2], acc[3]);
}

// ---------------------------------------------------------------------------

static inline int cdiv(long long a, int b) { return (int)((a + b - 1) / b); }

extern "C" void kernel_launch(void* const* d_in, const int* in_sizes, int n_in,
                              void* d_out, int out_size) {
    (void)in_sizes; (void)n_in; (void)out_size;
    const float* x    = (const float*)d_in[0];
    const float* efet = (const float*)d_in[1];
    const int*   src  = (const int*)d_in[2];
    const int*   dst  = (const int*)d_in[3];
    const float* W1 = (const float*)d_in[4];  const float* b1 = (const float*)d_in[5];
    const float* W2 = (const float*)d_in[6];  const float* b2 = (const float*)d_in[7];
    const float* W3 = (const float*)d_in[8];  const float* b3 = (const float*)d_in[9];
    const float* W4 = (const float*)d_in[10]; const float* b4 = (const float*)d_in[11];
    const float* W5 = (const float*)d_in[12]; const float* b5 = (const float*)d_in[13];
    float* out = (float*)d_out;

    float *bufA, *bufB, *bufC;
    int *ideg, *odeg, *cnt, *hist, *hcnt;
    __half *w2t, *w3t, *w4t;
    cudaGetSymbolAddress((void**)&bufA, g_bufA);
    cudaGetSymbolAddress((void**)&bufB, g_bufB);
    cudaGetSymbolAddress((void**)&bufC, g_bufC);
    cudaGetSymbolAddress((void**)&ideg, g_ideg);
    cudaGetSymbolAddress((void**)&odeg, g_odeg);
    cudaGetSymbolAddress((void**)&cnt,  g_cnt);
    cudaGetSymbolAddress((void**)&hist, g_hist);
    cudaGetSymbolAddress((void**)&hcnt, g_hcnt);
    cudaGetSymbolAddress((void**)&w2t, g_w2t);
    cudaGetSymbolAddress((void**)&w3t, g_w3t);
    cudaGetSymbolAddress((void**)&w4t, g_w4t);
    __half* hA = (__half*)bufA;
    __half* hB = (__half*)bufB;
    __half* hC = (__half*)bufC;

    const int TB = 256;

    // ---- preprocessing: degrees, norms, CSR, degree-sorted perm, fp16 weights
    cudaMemsetAsync(ideg, 0, NN * sizeof(int));
    cudaMemsetAsync(odeg, 0, NN * sizeof(int));
    cudaMemsetAsync(cnt,  0, NN * sizeof(int));
    cudaMemsetAsync(hist, 0, 256 * sizeof(int));
    cudaMemsetAsync(hcnt, 0, 256 * sizeof(int));
    deg_k<<<cdiv(NE, TB), TB>>>(src, dst);
    norm_k<<<cdiv(NN, TB), TB>>>();
    scan_k<<<1, 1024>>>();
    hist_k<<<cdiv(NN, TB), TB>>>();
    hscan_k<<<1, 256>>>();
    permfill_k<<<cdiv(NN, TB), TB>>>();
    fill_k<<<cdiv(NE, TB), TB>>>(src, dst, efet);
    wcvt_k<256, 128><<<cdiv(256 * 128, TB), TB>>>(W2, w2t);
    wcvt_k<128, 64><<<cdiv(128 * 64, TB), TB>>>(W3, w3t);
    wcvt_k<64, 32><<<cdiv(64 * 32, TB), TB>>>(W4, w4t);

    // ---- gc1: pre-aggregate 16-wide scaled x, matmul+epi+relu -> g1 fp16
    gather_k<16, 2, false, false><<<cdiv(NN, 64), TB>>>(x, nullptr, bufA);
    gemm1_k<<<cdiv(NN, 64), TB>>>(bufA, W1, b1, hB);                          // g1: hB

    // ---- y1 = g1 @ W2 (mma 256->128) BEFORE ewa1 (commuted)
    mma_gemm_k<256, 128><<<cdiv(NN, 64), TB>>>(hB, w2t, hA);                  // y1: hA
    // ---- ewa1 at width 128: m2 = ewa(y1) * out_norm (relu is identity)
    gather_h_k<128, 1, false, false, true, true><<<cdiv(NN, 16), TB>>>(hA, nullptr, hC);
    // ---- gc2 aggregation: g2 = relu(agg(m2)*ni + b2)
    gather_h_k<128, 0, true, true, false, true><<<cdiv(NN, 16), TB>>>(hC, b2, hB); // g2: hB

    // ---- y2 = g2 @ W3 (mma 128->64) BEFORE ewa2
    mma_gemm_k<128, 64><<<cdiv(NN, 128), TB>>>(hB, w3t, hA);                  // y2: hA
    // ---- ewa2 at width 64
    gather_h_k<64, 1, false, false, true, true><<<cdiv(NN, 32), TB>>>(hA, nullptr, hC);
    // ---- gc3 aggregation: g3 = relu(agg(m3)*ni + b3)
    gather_h_k<64, 0, true, true, false, true><<<cdiv(NN, 32), TB>>>(hC, b3, hB);  // g3: hB

    // ---- y3 = g3 @ W4 (mma 64->32) BEFORE ewa3
    mma_gemm_k<64, 32><<<cdiv(NN, 128), TB>>>(hB, w4t, hA);                   // y3: hA
    // ---- ewa3 at width 32
    gather_h_k<32, 1, false, false, true, true><<<cdiv(NN, 64), TB>>>(hA, nullptr, hC);
    // ---- gc4 aggregation: h4 = relu(agg(m4)*ni + b4) -> fp32
    gather_h_k<32, 0, true, true, false, false><<<cdiv(NN, 64), TB>>>(hC, b4, bufB);

    // ---- gc5: m5 = (h4*no) @ W5, then agg*ni + b5
    gemm5_k<<<cdiv(NN, 256), TB>>>(bufB, W5, bufA);                           // m5: bufA
    gather_k<4, 0, true, false><<<cdiv(NN, 256), TB>>>(bufA, b5, out);
}

// round 13
// speedup vs baseline: 1.1442x; 1.1442x over previous
#include <cuda_runtime.h>
#include <cuda_fp16.h>
#include <cuda_bf16.h>
#include <cstddef>
#include <cstdint>

// ---------------------------------------------------------------------------
// GCN: 5 GraphConv + 3 edge-weighted aggregations. CSR-gather + tensor cores.
// R13 = R11 (297.0us: commuted ewa/matmul, R5 preprocessing, 8-half gathers)
//       + g1 fusion (pre-agg + gemm1) + g45 fusion (gc4-agg + gemm5).
// Both fusions preserve gather thread-parallelism (4 threads/node) — R7 vs R8
// showed them neutral-to-positive. R12's degree-sort permutation regressed
// (store de-coalescing + preproc cost) and is dropped.
// ---------------------------------------------------------------------------

#define NN 50000
#define NE 800000

__device__ int   g_ideg[NN];
__device__ int   g_odeg[NN];
__device__ int   g_cnt[NN];
__device__ int   g_off[NN + 1];
__device__ __align__(16) int2  g_edge[NE];   // {src, __float_as_int(efet)}
__device__ float g_norm_out[NN];
__device__ float g_norm_in[NN];
__device__ __align__(16) float g_bufA[(size_t)NN * 256];
__device__ __align__(16) float g_bufB[(size_t)NN * 256];
__device__ __align__(16) float g_bufC[(size_t)NN * 256];
// transposed fp16 weights: W2t[128][256], W3t[64][128], W4t[32][64]
__device__ __align__(16) __half g_w2t[128 * 256];
__device__ __align__(16) __half g_w3t[64 * 128];
__device__ __align__(16) __half g_w4t[32 * 64];

// ---- degrees / norms -------------------------------------------------------

__global__ void deg_k(const int* __restrict__ src, const int* __restrict__ dst) {
    int e = blockIdx.x * blockDim.x + threadIdx.x;
    if (e < NE) {
        atomicAdd(&g_odeg[src[e]], 1);
        atomicAdd(&g_ideg[dst[e]], 1);
    }
}

__global__ void norm_k() {
    int i = blockIdx.x * blockDim.x + threadIdx.x;
    if (i < NN) {
        g_norm_out[i] = rsqrtf(fmaxf((float)g_odeg[i], 1.0f));
        g_norm_in[i]  = rsqrtf(fmaxf((float)g_ideg[i], 1.0f));
    }
}

// ---- exclusive scan of in-degrees -> CSR offsets (single block) ------------

__global__ void scan_k() {
    __shared__ int sh[1024];
    const int t = threadIdx.x;
    const int CH = (NN + 1023) / 1024;
    int beg = t * CH, end = min(beg + CH, NN);
    int s = 0;
    for (int i = beg; i < end; i++) s += g_ideg[i];
    sh[t] = s;
    __syncthreads();
    for (int ofs = 1; ofs < 1024; ofs <<= 1) {
        int v = (t >= ofs) ? sh[t - ofs] : 0;
        __syncthreads();
        sh[t] += v;
        __syncthreads();
    }
    int run = (t == 0) ? 0 : sh[t - 1];
    for (int i = beg; i < end; i++) { g_off[i] = run; run += g_ideg[i]; }
    if (end == NN) g_off[NN] = run;
}

__global__ void fill_k(const int* __restrict__ src, const int* __restrict__ dst,
                       const float* __restrict__ efet) {
    int e = blockIdx.x * blockDim.x + threadIdx.x;
    if (e < NE) {
        int d = dst[e];
        int pos = g_off[d] + atomicAdd(&g_cnt[d], 1);
        g_edge[pos] = make_int2(src[e], __float_as_int(efet[e]));
    }
}

// ---- W -> Wt fp16 transpose (tiny) -----------------------------------------

template <int K, int N>
__global__ void wcvt_k(const float* __restrict__ W, __half* __restrict__ Wt) {
    int i = blockIdx.x * blockDim.x + threadIdx.x;
    if (i < K * N) {
        int k = i / N, n = i % N;
        Wt[(size_t)n * K + k] = __float2half(W[i]);
    }
}

// ---- fp32 gather (final 4-wide) --------------------------------------------
// WMODE: 0 = w=1, 1 = w=efet, 2 = w=out_norm[src]

template <int F, int WMODE, bool EPI, bool RELU>
__global__ void gather_k(const float* __restrict__ m,
                         const float* __restrict__ b,
                         float* __restrict__ out) {
    constexpr int NT = F / 4;
    constexpr int NPB = 256 / NT;
    int t = threadIdx.x;
    int node = blockIdx.x * NPB + t / NT;
    int c = t % NT;
    if (node >= NN) return;
    int beg = g_off[node], end = g_off[node + 1];

    float4 acc = make_float4(0.f, 0.f, 0.f, 0.f);
    for (int e = beg; e < end; e++) {
        int2 sc = g_edge[e];
        int s = sc.x;
        float w = 1.0f;
        if (WMODE == 1) w = __int_as_float(sc.y);
        if (WMODE == 2) w = g_norm_out[s];
        float4 v = *(const float4*)(m + (size_t)s * F + c * 4);
        acc.x += v.x * w; acc.y += v.y * w; acc.z += v.z * w; acc.w += v.w * w;
    }
    if (EPI) {
        float ni = g_norm_in[node];
        acc.x = acc.x * ni + b[c * 4 + 0];
        acc.y = acc.y * ni + b[c * 4 + 1];
        acc.z = acc.z * ni + b[c * 4 + 2];
        acc.w = acc.w * ni + b[c * 4 + 3];
    }
    if (RELU) {
        acc.x = fmaxf(acc.x, 0.f); acc.y = fmaxf(acc.y, 0.f);
        acc.z = fmaxf(acc.z, 0.f); acc.w = fmaxf(acc.w, 0.f);
    }
    *(float4*)(out + (size_t)node * F + c * 4) = acc;
}

// ---- fp16-input gather ------------------------------------------------------
// 8 halves per thread, fp32 accumulation, x2 edge unroll (frozen config).
// ONORM: multiply final result by out_norm[node].  OH: fp16 output.

__device__ __forceinline__ void acc8(float* a, uint4 r, float w) {
    float2 f;
    f = __half22float2(*(const __half2*)&r.x); a[0] += f.x * w; a[1] += f.y * w;
    f = __half22float2(*(const __half2*)&r.y); a[2] += f.x * w; a[3] += f.y * w;
    f = __half22float2(*(const __half2*)&r.z); a[4] += f.x * w; a[5] += f.y * w;
    f = __half22float2(*(const __half2*)&r.w); a[6] += f.x * w; a[7] += f.y * w;
}

template <int F, int WMODE, bool EPI, bool RELU, bool ONORM, bool OH>
__global__ void gather_h_k(const __half* __restrict__ m,
                           const float* __restrict__ b,
                           void* __restrict__ outp) {
    constexpr int NT = F / 8;
    constexpr int NPB = 256 / NT;
    int t = threadIdx.x;
    int node = blockIdx.x * NPB + t / NT;
    int c = t % NT;
    if (node >= NN) return;
    int beg = g_off[node], end = g_off[node + 1];

    float acc[8];
#pragma unroll
    for (int i = 0; i < 8; i++) acc[i] = 0.f;

    const uint4* base = (const uint4*)m;
    int e = beg;
    for (; e + 2 <= end; e += 2) {
        int2 sc0 = g_edge[e], sc1 = g_edge[e + 1];
        float w0 = 1.f, w1 = 1.f;
        if (WMODE == 1) { w0 = __int_as_float(sc0.y); w1 = __int_as_float(sc1.y); }
        uint4 r0 = base[(size_t)sc0.x * NT + c];
        uint4 r1 = base[(size_t)sc1.x * NT + c];
        acc8(acc, r0, w0);
        acc8(acc, r1, w1);
    }
    if (e < end) {
        int2 sc = g_edge[e];
        float w = (WMODE == 1) ? __int_as_float(sc.y) : 1.f;
        uint4 r = base[(size_t)sc.x * NT + c];
        acc8(acc, r, w);
    }

    if (EPI) {
        float ni = g_norm_in[node];
#pragma unroll
        for (int i = 0; i < 8; i++) acc[i] = acc[i] * ni + b[c * 8 + i];
    }
    if (RELU) {
#pragma unroll
        for (int i = 0; i < 8; i++) acc[i] = fmaxf(acc[i], 0.f);
    }
    if (ONORM) {
        float no = g_norm_out[node];
#pragma unroll
        for (int i = 0; i < 8; i++) acc[i] *= no;
    }
    if (OH) {
        __half2 h0 = __floats2half2_rn(acc[0], acc[1]);
        __half2 h1 = __floats2half2_rn(acc[2], acc[3]);
        __half2 h2 = __floats2half2_rn(acc[4], acc[5]);
        __half2 h3 = __floats2half2_rn(acc[6], acc[7]);
        uint4 r;
        r.x = *(const unsigned*)&h0; r.y = *(const unsigned*)&h1;
        r.z = *(const unsigned*)&h2; r.w = *(const unsigned*)&h3;
        ((uint4*)outp)[(size_t)node * NT + c] = r;
    } else {
        float* o = (float*)outp + (size_t)node * F + c * 8;
        *(float4*)(o + 0) = make_float4(acc[0], acc[1], acc[2], acc[3]);
        *(float4*)(o + 4) = make_float4(acc[4], acc[5], acc[6], acc[7]);
    }
}

// ---- tensor-core GEMM: D[M,N] = A[M,K] @ W[K,N], fp16 in / fp32 acc --------

template <int K, int N>
__global__ void mma_gemm_k(const __half* __restrict__ A,
                           const __half* __restrict__ Wt,
                           __half* __restrict__ D) {
    constexpr int WN = (N >= 64) ? 64 : N;       // warp n-extent
    constexpr int TN = WN / 8;                   // n8 tiles per warp
    constexpr int WARPS_N = N / WN;
    constexpr int WARPS_M = 8 / WARPS_N;
    constexpr int BM = WARPS_M * 16;
    constexpr int PITCH = K + 8;                 // +16B pad -> bank rotation
    constexpr int KC = K / 16;                   // k16 chunks

    __shared__ __half sA[BM * PITCH];

    const int tid = threadIdx.x;
    const int lane = tid & 31;
    const int wid = tid >> 5;
    const int wm = wid % WARPS_M;
    const int wn = wid / WARPS_M;
    const int blockStart = blockIdx.x * BM;

    for (int i = tid; i < BM * (K / 8); i += 256) {
        int row = i / (K / 8), chunk = i % (K / 8);
        int node = blockStart + row;
        uint4 v = make_uint4(0, 0, 0, 0);
        if (node < NN) v = ((const uint4*)A)[(size_t)node * (K / 8) + chunk];
        *(uint4*)(&sA[row * PITCH + chunk * 8]) = v;
    }
    __syncthreads();

    float acc[TN][4];
#pragma unroll
    for (int t = 0; t < TN; t++)
#pragma unroll
        for (int i = 0; i < 4; i++) acc[t][i] = 0.f;

    const int q = lane >> 3, r = lane & 7;
    const int arow = wm * 16 + r + 8 * (q & 1);
    const int acol0 = 8 * (q >> 1);
    unsigned abase;
    {
        const void* p = &sA[arow * PITCH + acol0];
        asm("{ .reg .u64 t; cvta.to.shared.u64 t, %1; cvt.u32.u64 %0, t; }"
            : "=r"(abase) : "l"(p));
    }

    const __half* wbase = Wt + (size_t)(wn * WN + (lane >> 2)) * K + (lane & 3) * 2;

#pragma unroll
    for (int kc = 0; kc < KC; kc++) {
        unsigned a0, a1, a2, a3;
        asm volatile("ldmatrix.sync.aligned.m8n8.x4.shared.b16 {%0,%1,%2,%3}, [%4];"
                     : "=r"(a0), "=r"(a1), "=r"(a2), "=r"(a3)
                     : "r"(abase + kc * 32));
#pragma unroll
        for (int tn = 0; tn < TN; tn++) {
            unsigned b0 = *(const unsigned*)(wbase + (size_t)tn * 8 * K + kc * 16);
            unsigned b1 = *(const unsigned*)(wbase + (size_t)tn * 8 * K + kc * 16 + 8);
            asm volatile(
                "mma.sync.aligned.m16n8k16.row.col.f32.f16.f16.f32 "
                "{%0,%1,%2,%3}, {%4,%5,%6,%7}, {%8,%9}, {%0,%1,%2,%3};"
                : "+f"(acc[tn][0]), "+f"(acc[tn][1]), "+f"(acc[tn][2]), "+f"(acc[tn][3])
                : "r"(a0), "r"(a1), "r"(a2), "r"(a3), "r"(b0), "r"(b1));
        }
    }

    const int node0 = blockStart + wm * 16 + (lane >> 2);
    const int node1 = node0 + 8;
#pragma unroll
    for (int tn = 0; tn < TN; tn++) {
        int gcol = wn * WN + tn * 8 + (lane & 3) * 2;
        if (node0 < NN) {
            __half2 h = __floats2half2_rn(acc[tn][0], acc[tn][1]);
            *(unsigned*)(D + (size_t)node0 * N + gcol) = *(const unsigned*)&h;
        }
        if (node1 < NN) {
            __half2 h = __floats2half2_rn(acc[tn][2], acc[tn][3]);
            *(unsigned*)(D + (size_t)node1 * N + gcol) = *(const unsigned*)&h;
        }
    }
}

// ---- fused gc1: gather 16-wide scaled x + (agg @ W1)*in_norm+b1, relu ------
// Gather phase: 4 threads/node (same parallelism as standalone gather_k<16,2>).

__global__ void g1_k(const float* __restrict__ x, const float* __restrict__ W1,
                     const float* __restrict__ b1, __half* __restrict__ out) {
    __shared__ float sX[64 * 16];
    const int tid = threadIdx.x;
    const int nbase = blockIdx.x * 64;

    {
        int g = tid / 4, c = tid % 4;
        int node = nbase + g;
        float4 a = make_float4(0.f, 0.f, 0.f, 0.f);
        if (node < NN) {
            int beg = g_off[node], end = g_off[node + 1];
            for (int e = beg; e < end; e++) {
                int s = g_edge[e].x;
                float w = g_norm_out[s];
                float4 v = *(const float4*)(x + (size_t)s * 16 + c * 4);
                a.x += v.x * w; a.y += v.y * w; a.z += v.z * w; a.w += v.w * w;
            }
        }
        *(float4*)(&sX[g * 16 + c * 4]) = a;
    }
    __syncthreads();

    const int j = tid;
    float w[16];
#pragma unroll
    for (int k = 0; k < 16; k++) w[k] = W1[k * 256 + j];
    float bj = b1[j];
#pragma unroll 4
    for (int ln = 0; ln < 64; ln++) {
        int node = nbase + ln;
        if (node >= NN) break;
        float acc = 0.f;
#pragma unroll
        for (int k = 0; k < 16; k++) acc += sX[ln * 16 + k] * w[k];
        acc = acc * g_norm_in[node] + bj;
        out[(size_t)node * 256 + j] = __float2half(fmaxf(acc, 0.f));
    }
}

// ---- fused gc4-agg + gemm5: h4 = relu(agg(m4)*ni+b4); m5 = (h4*no)@W5 ------
// Gather phase: 4 threads/node over fp16 m4 (width 32, 8 halves/thread).

__global__ void g45_k(const __half* __restrict__ m4, const float* __restrict__ b4,
                      const float* __restrict__ W5, float* __restrict__ m5) {
    __shared__ float sH[64 * 32];
    __shared__ float sW[32 * 4];
    const int tid = threadIdx.x;
    if (tid < 128) sW[tid] = W5[tid];
    const int g = tid / 4, c = tid % 4;     // 64 nodes x 4 threads
    const int node = blockIdx.x * 64 + g;

    float acc[8];
#pragma unroll
    for (int i = 0; i < 8; i++) acc[i] = 0.f;
    if (node < NN) {
        int beg = g_off[node], end = g_off[node + 1];
        const uint4* base = (const uint4*)m4;     // row stride = 4 uint4s
        int e = beg;
        for (; e + 2 <= end; e += 2) {
            int2 sc0 = g_edge[e], sc1 = g_edge[e + 1];
            uint4 r0 = base[(size_t)sc0.x * 4 + c];
            uint4 r1 = base[(size_t)sc1.x * 4 + c];
            acc8(acc, r0, 1.f);
            acc8(acc, r1, 1.f);
        }
        if (e < end) {
            int2 sc = g_edge[e];
            uint4 r = base[(size_t)sc.x * 4 + c];
            acc8(acc, r, 1.f);
        }
        float ni = g_norm_in[node];
        float no = g_norm_out[node];
#pragma unroll
        for (int i = 0; i < 8; i++)
            acc[i] = fmaxf(acc[i] * ni + b4[c * 8 + i], 0.f) * no;
    }
#pragma unroll
    for (int i = 0; i < 8; i++) sH[g * 32 + c * 8 + i] = acc[i];
    __syncthreads();

    if (node >= NN) return;
    float o = 0.f;
#pragma unroll
    for (int k = 0; k < 32; k++) o += sH[g * 32 + k] * sW[k * 4 + c];
    m5[(size_t)node * 4 + c] = o;
}

// ---------------------------------------------------------------------------

static inline int cdiv(long long a, int b) { return (int)((a + b - 1) / b); }

extern "C" void kernel_launch(void* const* d_in, const int* in_sizes, int n_in,
                              void* d_out, int out_size) {
    (void)in_sizes; (void)n_in; (void)out_size;
    const float* x    = (const float*)d_in[0];
    const float* efet = (const float*)d_in[1];
    const int*   src  = (const int*)d_in[2];
    const int*   dst  = (const int*)d_in[3];
    const float* W1 = (const float*)d_in[4];  const float* b1 = (const float*)d_in[5];
    const float* W2 = (const float*)d_in[6];  const float* b2 = (const float*)d_in[7];
    const float* W3 = (const float*)d_in[8];  const float* b3 = (const float*)d_in[9];
    const float* W4 = (const float*)d_in[10]; const float* b4 = (const float*)d_in[11];
    const float* W5 = (const float*)d_in[12]; const float* b5 = (const float*)d_in[13];
    float* out = (float*)d_out;

    float *bufA, *bufB, *bufC;
    int *ideg, *odeg, *cnt;
    __half *w2t, *w3t, *w4t;
    cudaGetSymbolAddress((void**)&bufA, g_bufA);
    cudaGetSymbolAddress((void**)&bufB, g_bufB);
    cudaGetSymbolAddress((void**)&bufC, g_bufC);
    cudaGetSymbolAddress((void**)&ideg, g_ideg);
    cudaGetSymbolAddress((void**)&odeg, g_odeg);
    cudaGetSymbolAddress((void**)&cnt,  g_cnt);
    cudaGetSymbolAddress((void**)&w2t, g_w2t);
    cudaGetSymbolAddress((void**)&w3t, g_w3t);
    cudaGetSymbolAddress((void**)&w4t, g_w4t);
    __half* hA = (__half*)bufA;
    __half* hB = (__half*)bufB;
    __half* hC = (__half*)bufC;

    const int TB = 256;

    // ---- preprocessing: degrees, norms, CSR, fp16 transposed weights (R5 form)
    cudaMemsetAsync(ideg, 0, NN * sizeof(int));
    cudaMemsetAsync(odeg, 0, NN * sizeof(int));
    cudaMemsetAsync(cnt,  0, NN * sizeof(int));
    deg_k<<<cdiv(NE, TB), TB>>>(src, dst);
    norm_k<<<cdiv(NN, TB), TB>>>();
    scan_k<<<1, 1024>>>();
    fill_k<<<cdiv(NE, TB), TB>>>(src, dst, efet);
    wcvt_k<256, 128><<<cdiv(256 * 128, TB), TB>>>(W2, w2t);
    wcvt_k<128, 64><<<cdiv(128 * 64, TB), TB>>>(W3, w3t);
    wcvt_k<64, 32><<<cdiv(64 * 32, TB), TB>>>(W4, w4t);

    // ---- gc1 fused: g1 = relu((agg16(x*no) @ W1)*ni + b1) -> fp16
    g1_k<<<cdiv(NN, 64), TB>>>(x, W1, b1, hB);                                // g1: hB

    // ---- y1 = g1 @ W2 (mma 256->128) BEFORE ewa1 (commuted)
    mma_gemm_k<256, 128><<<cdiv(NN, 64), TB>>>(hB, w2t, hA);                  // y1: hA
    // ---- ewa1 at width 128: m2 = ewa(y1) * out_norm (relu is identity)
    gather_h_k<128, 1, false, false, true, true><<<cdiv(NN, 16), TB>>>(hA, nullptr, hC);
    // ---- gc2 aggregation: g2 = relu(agg(m2)*ni + b2)
    gather_h_k<128, 0, true, true, false, true><<<cdiv(NN, 16), TB>>>(hC, b2, hB); // g2: hB

    // ---- y2 = g2 @ W3 (mma 128->64) BEFORE ewa2
    mma_gemm_k<128, 64><<<cdiv(NN, 128), TB>>>(hB, w3t, hA);                  // y2: hA
    // ---- ewa2 at width 64
    gather_h_k<64, 1, false, false, true, true><<<cdiv(NN, 32), TB>>>(hA, nullptr, hC);
    // ---- gc3 aggregation: g3 = relu(agg(m3)*ni + b3)
    gather_h_k<64, 0, true, true, false, true><<<cdiv(NN, 32), TB>>>(hC, b3, hB);  // g3: hB

    // ---- y3 = g3 @ W4 (mma 64->32) BEFORE ewa3
    mma_gemm_k<64, 32><<<cdiv(NN, 128), TB>>>(hB, w4t, hA);                   // y3: hA
    // ---- ewa3 at width 32
    gather_h_k<32, 1, false, false, true, true><<<cdiv(NN, 64), TB>>>(hA, nullptr, hC);

    // ---- gc4-agg + gemm5 fused: m5 = (relu(agg(m4)*ni+b4)*no) @ W5
    g45_k<<<cdiv(NN, 64), TB>>>(hC, b4, W5, bufB);                            // m5: bufB

    // ---- gc5 aggregation: out = agg(m5)*ni + b5
    gather_k<4, 0, true, false><<<cdiv(NN, 256), TB>>>(bufB, b5, out);
}

// round 14
// speedup vs baseline: 1.3335x; 1.1654x over previous
#include <cuda_runtime.h>
#include <cuda_fp16.h>
#include <cuda_bf16.h>
#include <cstddef>
#include <cstdint>

// ---------------------------------------------------------------------------
// GCN: 5 GraphConv + 3 edge-weighted aggregations. CSR-gather + tensor cores.
// R14 = R13 (291.6us) with ONE change: the single-block scan_k (1024 threads
// on one SM doing ~200k uncoalesced 196B-strided sectors, est. 15-25us — and
// the likely mechanism behind R8's +70us scan_norm_k regression) replaced by
// a 3-phase multi-block scan (coalesced, spread over 196 SMs, ~5us total).
// Hot path byte-frozen from R13.
// ---------------------------------------------------------------------------

#define NN 50000
#define NE 800000

__device__ int   g_ideg[NN];
__device__ int   g_odeg[NN];
__device__ int   g_cnt[NN];
__device__ int   g_off[NN + 1];
__device__ int   g_bsum[256];
__device__ int   g_boff[256];
__device__ __align__(16) int2  g_edge[NE];   // {src, __float_as_int(efet)}
__device__ float g_norm_out[NN];
__device__ float g_norm_in[NN];
__device__ __align__(16) float g_bufA[(size_t)NN * 256];
__device__ __align__(16) float g_bufB[(size_t)NN * 256];
__device__ __align__(16) float g_bufC[(size_t)NN * 256];
// transposed fp16 weights: W2t[128][256], W3t[64][128], W4t[32][64]
__device__ __align__(16) __half g_w2t[128 * 256];
__device__ __align__(16) __half g_w3t[64 * 128];
__device__ __align__(16) __half g_w4t[32 * 64];

// ---- degrees / norms -------------------------------------------------------

__global__ void deg_k(const int* __restrict__ src, const int* __restrict__ dst) {
    int e = blockIdx.x * blockDim.x + threadIdx.x;
    if (e < NE) {
        atomicAdd(&g_odeg[src[e]], 1);
        atomicAdd(&g_ideg[dst[e]], 1);
    }
}

__global__ void norm_k() {
    int i = blockIdx.x * blockDim.x + threadIdx.x;
    if (i < NN) {
        g_norm_out[i] = rsqrtf(fmaxf((float)g_odeg[i], 1.0f));
        g_norm_in[i]  = rsqrtf(fmaxf((float)g_ideg[i], 1.0f));
    }
}

// ---- multi-block exclusive scan of in-degrees -> CSR offsets ---------------
// Phase 1: per-block (256-wide) local exclusive scan, coalesced; emit sums.

__global__ void bscan_k() {
    __shared__ int sh[256];
    int t = threadIdx.x;
    int i = blockIdx.x * 256 + t;
    int v = (i < NN) ? g_ideg[i] : 0;
    sh[t] = v;
    __syncthreads();
    for (int o = 1; o < 256; o <<= 1) {
        int u = (t >= o) ? sh[t - o] : 0;
        __syncthreads();
        sh[t] += u;
        __syncthreads();
    }
    if (i < NN) g_off[i] = sh[t] - v;                  // local exclusive
    if (t == 255) g_bsum[blockIdx.x] = sh[255];
}

// Phase 2: single tiny block scans the 196 block sums; total is NE by def.

__global__ void bsum_k() {
    __shared__ int sh[256];
    const int NB = (NN + 255) / 256;
    int t = threadIdx.x;
    int v = (t < NB) ? g_bsum[t] : 0;
    sh[t] = v;
    __syncthreads();
    for (int o = 1; o < 256; o <<= 1) {
        int u = (t >= o) ? sh[t - o] : 0;
        __syncthreads();
        sh[t] += u;
        __syncthreads();
    }
    if (t < NB) g_boff[t] = sh[t] - v;                 // exclusive block offset
    if (t == 0) g_off[NN] = NE;
}

// Phase 3: add block offsets, coalesced.

__global__ void badd_k() {
    int i = blockIdx.x * 256 + threadIdx.x;
    if (i < NN) g_off[i] += g_boff[blockIdx.x];
}

__global__ void fill_k(const int* __restrict__ src, const int* __restrict__ dst,
                       const float* __restrict__ efet) {
    int e = blockIdx.x * blockDim.x + threadIdx.x;
    if (e < NE) {
        int d = dst[e];
        int pos = g_off[d] + atomicAdd(&g_cnt[d], 1);
        g_edge[pos] = make_int2(src[e], __float_as_int(efet[e]));
    }
}

// ---- W -> Wt fp16 transpose (tiny) -----------------------------------------

template <int K, int N>
__global__ void wcvt_k(const float* __restrict__ W, __half* __restrict__ Wt) {
    int i = blockIdx.x * blockDim.x + threadIdx.x;
    if (i < K * N) {
        int k = i / N, n = i % N;
        Wt[(size_t)n * K + k] = __float2half(W[i]);
    }
}

// ---- fp32 gather (final 4-wide) --------------------------------------------
// WMODE: 0 = w=1, 1 = w=efet, 2 = w=out_norm[src]

template <int F, int WMODE, bool EPI, bool RELU>
__global__ void gather_k(const float* __restrict__ m,
                         const float* __restrict__ b,
                         float* __restrict__ out) {
    constexpr int NT = F / 4;
    constexpr int NPB = 256 / NT;
    int t = threadIdx.x;
    int node = blockIdx.x * NPB + t / NT;
    int c = t % NT;
    if (node >= NN) return;
    int beg = g_off[node], end = g_off[node + 1];

    float4 acc = make_float4(0.f, 0.f, 0.f, 0.f);
    for (int e = beg; e < end; e++) {
        int2 sc = g_edge[e];
        int s = sc.x;
        float w = 1.0f;
        if (WMODE == 1) w = __int_as_float(sc.y);
        if (WMODE == 2) w = g_norm_out[s];
        float4 v = *(const float4*)(m + (size_t)s * F + c * 4);
        acc.x += v.x * w; acc.y += v.y * w; acc.z += v.z * w; acc.w += v.w * w;
    }
    if (EPI) {
        float ni = g_norm_in[node];
        acc.x = acc.x * ni + b[c * 4 + 0];
        acc.y = acc.y * ni + b[c * 4 + 1];
        acc.z = acc.z * ni + b[c * 4 + 2];
        acc.w = acc.w * ni + b[c * 4 + 3];
    }
    if (RELU) {
        acc.x = fmaxf(acc.x, 0.f); acc.y = fmaxf(acc.y, 0.f);
        acc.z = fmaxf(acc.z, 0.f); acc.w = fmaxf(acc.w, 0.f);
    }
    *(float4*)(out + (size_t)node * F + c * 4) = acc;
}

// ---- fp16-input gather ------------------------------------------------------
// 8 halves per thread, fp32 accumulation, x2 edge unroll (frozen config).
// ONORM: multiply final result by out_norm[node].  OH: fp16 output.

__device__ __forceinline__ void acc8(float* a, uint4 r, float w) {
    float2 f;
    f = __half22float2(*(const __half2*)&r.x); a[0] += f.x * w; a[1] += f.y * w;
    f = __half22float2(*(const __half2*)&r.y); a[2] += f.x * w; a[3] += f.y * w;
    f = __half22float2(*(const __half2*)&r.z); a[4] += f.x * w; a[5] += f.y * w;
    f = __half22float2(*(const __half2*)&r.w); a[6] += f.x * w; a[7] += f.y * w;
}

template <int F, int WMODE, bool EPI, bool RELU, bool ONORM, bool OH>
__global__ void gather_h_k(const __half* __restrict__ m,
                           const float* __restrict__ b,
                           void* __restrict__ outp) {
    constexpr int NT = F / 8;
    constexpr int NPB = 256 / NT;
    int t = threadIdx.x;
    int node = blockIdx.x * NPB + t / NT;
    int c = t % NT;
    if (node >= NN) return;
    int beg = g_off[node], end = g_off[node + 1];

    float acc[8];
#pragma unroll
    for (int i = 0; i < 8; i++) acc[i] = 0.f;

    const uint4* base = (const uint4*)m;
    int e = beg;
    for (; e + 2 <= end; e += 2) {
        int2 sc0 = g_edge[e], sc1 = g_edge[e + 1];
        float w0 = 1.f, w1 = 1.f;
        if (WMODE == 1) { w0 = __int_as_float(sc0.y); w1 = __int_as_float(sc1.y); }
        uint4 r0 = base[(size_t)sc0.x * NT + c];
        uint4 r1 = base[(size_t)sc1.x * NT + c];
        acc8(acc, r0, w0);
        acc8(acc, r1, w1);
    }
    if (e < end) {
        int2 sc = g_edge[e];
        float w = (WMODE == 1) ? __int_as_float(sc.y) : 1.f;
        uint4 r = base[(size_t)sc.x * NT + c];
        acc8(acc, r, w);
    }

    if (EPI) {
        float ni = g_norm_in[node];
#pragma unroll
        for (int i = 0; i < 8; i++) acc[i] = acc[i] * ni + b[c * 8 + i];
    }
    if (RELU) {
#pragma unroll
        for (int i = 0; i < 8; i++) acc[i] = fmaxf(acc[i], 0.f);
    }
    if (ONORM) {
        float no = g_norm_out[node];
#pragma unroll
        for (int i = 0; i < 8; i++) acc[i] *= no;
    }
    if (OH) {
        __half2 h0 = __floats2half2_rn(acc[0], acc[1]);
        __half2 h1 = __floats2half2_rn(acc[2], acc[3]);
        __half2 h2 = __floats2half2_rn(acc[4], acc[5]);
        __half2 h3 = __floats2half2_rn(acc[6], acc[7]);
        uint4 r;
        r.x = *(const unsigned*)&h0; r.y = *(const unsigned*)&h1;
        r.z = *(const unsigned*)&h2; r.w = *(const unsigned*)&h3;
        ((uint4*)outp)[(size_t)node * NT + c] = r;
    } else {
        float* o = (float*)outp + (size_t)node * F + c * 8;
        *(float4*)(o + 0) = make_float4(acc[0], acc[1], acc[2], acc[3]);
        *(float4*)(o + 4) = make_float4(acc[4], acc[5], acc[6], acc[7]);
    }
}

// ---- tensor-core GEMM: D[M,N] = A[M,K] @ W[K,N], fp16 in / fp32 acc --------

template <int K, int N>
__global__ void mma_gemm_k(const __half* __restrict__ A,
                           const __half* __restrict__ Wt,
                           __half* __restrict__ D) {
    constexpr int WN = (N >= 64) ? 64 : N;       // warp n-extent
    constexpr int TN = WN / 8;                   // n8 tiles per warp
    constexpr int WARPS_N = N / WN;
    constexpr int WARPS_M = 8 / WARPS_N;
    constexpr int BM = WARPS_M * 16;
    constexpr int PITCH = K + 8;                 // +16B pad -> bank rotation
    constexpr int KC = K / 16;                   // k16 chunks

    __shared__ __half sA[BM * PITCH];

    const int tid = threadIdx.x;
    const int lane = tid & 31;
    const int wid = tid >> 5;
    const int wm = wid % WARPS_M;
    const int wn = wid / WARPS_M;
    const int blockStart = blockIdx.x * BM;

    for (int i = tid; i < BM * (K / 8); i += 256) {
        int row = i / (K / 8), chunk = i % (K / 8);
        int node = blockStart + row;
        uint4 v = make_uint4(0, 0, 0, 0);
        if (node < NN) v = ((const uint4*)A)[(size_t)node * (K / 8) + chunk];
        *(uint4*)(&sA[row * PITCH + chunk * 8]) = v;
    }
    __syncthreads();

    float acc[TN][4];
#pragma unroll
    for (int t = 0; t < TN; t++)
#pragma unroll
        for (int i = 0; i < 4; i++) acc[t][i] = 0.f;

    const int q = lane >> 3, r = lane & 7;
    const int arow = wm * 16 + r + 8 * (q & 1);
    const int acol0 = 8 * (q >> 1);
    unsigned abase;
    {
        const void* p = &sA[arow * PITCH + acol0];
        asm("{ .reg .u64 t; cvta.to.shared.u64 t, %1; cvt.u32.u64 %0, t; }"
            : "=r"(abase) : "l"(p));
    }

    const __half* wbase = Wt + (size_t)(wn * WN + (lane >> 2)) * K + (lane & 3) * 2;

#pragma unroll
    for (int kc = 0; kc < KC; kc++) {
        unsigned a0, a1, a2, a3;
        asm volatile("ldmatrix.sync.aligned.m8n8.x4.shared.b16 {%0,%1,%2,%3}, [%4];"
                     : "=r"(a0), "=r"(a1), "=r"(a2), "=r"(a3)
                     : "r"(abase + kc * 32));
#pragma unroll
        for (int tn = 0; tn < TN; tn++) {
            unsigned b0 = *(const unsigned*)(wbase + (size_t)tn * 8 * K + kc * 16);
            unsigned b1 = *(const unsigned*)(wbase + (size_t)tn * 8 * K + kc * 16 + 8);
            asm volatile(
                "mma.sync.aligned.m16n8k16.row.col.f32.f16.f16.f32 "
                "{%0,%1,%2,%3}, {%4,%5,%6,%7}, {%8,%9}, {%0,%1,%2,%3};"
                : "+f"(acc[tn][0]), "+f"(acc[tn][1]), "+f"(acc[tn][2]), "+f"(acc[tn][3])
                : "r"(a0), "r"(a1), "r"(a2), "r"(a3), "r"(b0), "r"(b1));
        }
    }

    const int node0 = blockStart + wm * 16 + (lane >> 2);
    const int node1 = node0 + 8;
#pragma unroll
    for (int tn = 0; tn < TN; tn++) {
        int gcol = wn * WN + tn * 8 + (lane & 3) * 2;
        if (node0 < NN) {
            __half2 h = __floats2half2_rn(acc[tn][0], acc[tn][1]);
            *(unsigned*)(D + (size_t)node0 * N + gcol) = *(const unsigned*)&h;
        }
        if (node1 < NN) {
            __half2 h = __floats2half2_rn(acc[tn][2], acc[tn][3]);
            *(unsigned*)(D + (size_t)node1 * N + gcol) = *(const unsigned*)&h;
        }
    }
}

// ---- fused gc1: gather 16-wide scaled x + (agg @ W1)*in_norm+b1, relu ------

__global__ void g1_k(const float* __restrict__ x, const float* __restrict__ W1,
                     const float* __restrict__ b1, __half* __restrict__ out) {
    __shared__ float sX[64 * 16];
    const int tid = threadIdx.x;
    const int nbase = blockIdx.x * 64;

    {
        int g = tid / 4, c = tid % 4;
        int node = nbase + g;
        float4 a = make_float4(0.f, 0.f, 0.f, 0.f);
        if (node < NN) {
            int beg = g_off[node], end = g_off[node + 1];
            for (int e = beg; e < end; e++) {
                int s = g_edge[e].x;
                float w = g_norm_out[s];
                float4 v = *(const float4*)(x + (size_t)s * 16 + c * 4);
                a.x += v.x * w; a.y += v.y * w; a.z += v.z * w; a.w += v.w * w;
            }
        }
        *(float4*)(&sX[g * 16 + c * 4]) = a;
    }
    __syncthreads();

    const int j = tid;
    float w[16];
#pragma unroll
    for (int k = 0; k < 16; k++) w[k] = W1[k * 256 + j];
    float bj = b1[j];
#pragma unroll 4
    for (int ln = 0; ln < 64; ln++) {
        int node = nbase + ln;
        if (node >= NN) break;
        float acc = 0.f;
#pragma unroll
        for (int k = 0; k < 16; k++) acc += sX[ln * 16 + k] * w[k];
        acc = acc * g_norm_in[node] + bj;
        out[(size_t)node * 256 + j] = __float2half(fmaxf(acc, 0.f));
    }
}

// ---- fused gc4-agg + gemm5: h4 = relu(agg(m4)*ni+b4); m5 = (h4*no)@W5 ------

__global__ void g45_k(const __half* __restrict__ m4, const float* __restrict__ b4,
                      const float* __restrict__ W5, float* __restrict__ m5) {
    __shared__ float sH[64 * 32];
    __shared__ float sW[32 * 4];
    const int tid = threadIdx.x;
    if (tid < 128) sW[tid] = W5[tid];
    const int g = tid / 4, c = tid % 4;     // 64 nodes x 4 threads
    const int node = blockIdx.x * 64 + g;

    float acc[8];
#pragma unroll
    for (int i = 0; i < 8; i++) acc[i] = 0.f;
    if (node < NN) {
        int beg = g_off[node], end = g_off[node + 1];
        const uint4* base = (const uint4*)m4;     // row stride = 4 uint4s
        int e = beg;
        for (; e + 2 <= end; e += 2) {
            int2 sc0 = g_edge[e], sc1 = g_edge[e + 1];
            uint4 r0 = base[(size_t)sc0.x * 4 + c];
            uint4 r1 = base[(size_t)sc1.x * 4 + c];
            acc8(acc, r0, 1.f);
            acc8(acc, r1, 1.f);
        }
        if (e < end) {
            int2 sc = g_edge[e];
            uint4 r = base[(size_t)sc.x * 4 + c];
            acc8(acc, r, 1.f);
        }
        float ni = g_norm_in[node];
        float no = g_norm_out[node];
#pragma unroll
        for (int i = 0; i < 8; i++)
            acc[i] = fmaxf(acc[i] * ni + b4[c * 8 + i], 0.f) * no;
    }
#pragma unroll
    for (int i = 0; i < 8; i++) sH[g * 32 + c * 8 + i] = acc[i];
    __syncthreads();

    if (node >= NN) return;
    float o = 0.f;
#pragma unroll
    for (int k = 0; k < 32; k++) o += sH[g * 32 + k] * sW[k * 4 + c];
    m5[(size_t)node * 4 + c] = o;
}

// ---------------------------------------------------------------------------

static inline int cdiv(long long a, int b) { return (int)((a + b - 1) / b); }

extern "C" void kernel_launch(void* const* d_in, const int* in_sizes, int n_in,
                              void* d_out, int out_size) {
    (void)in_sizes; (void)n_in; (void)out_size;
    const float* x    = (const float*)d_in[0];
    const float* efet = (const float*)d_in[1];
    const int*   src  = (const int*)d_in[2];
    const int*   dst  = (const int*)d_in[3];
    const float* W1 = (const float*)d_in[4];  const float* b1 = (const float*)d_in[5];
    const float* W2 = (const float*)d_in[6];  const float* b2 = (const float*)d_in[7];
    const float* W3 = (const float*)d_in[8];  const float* b3 = (const float*)d_in[9];
    const float* W4 = (const float*)d_in[10]; const float* b4 = (const float*)d_in[11];
    const float* W5 = (const float*)d_in[12]; const float* b5 = (const float*)d_in[13];
    float* out = (float*)d_out;

    float *bufA, *bufB, *bufC;
    int *ideg, *odeg, *cnt;
    __half *w2t, *w3t, *w4t;
    cudaGetSymbolAddress((void**)&bufA, g_bufA);
    cudaGetSymbolAddress((void**)&bufB, g_bufB);
    cudaGetSymbolAddress((void**)&bufC, g_bufC);
    cudaGetSymbolAddress((void**)&ideg, g_ideg);
    cudaGetSymbolAddress((void**)&odeg, g_odeg);
    cudaGetSymbolAddress((void**)&cnt,  g_cnt);
    cudaGetSymbolAddress((void**)&w2t, g_w2t);
    cudaGetSymbolAddress((void**)&w3t, g_w3t);
    cudaGetSymbolAddress((void**)&w4t, g_w4t);
    __half* hA = (__half*)bufA;
    __half* hB = (__half*)bufB;
    __half* hC = (__half*)bufC;

    const int TB = 256;
    const int NB = cdiv(NN, 256);   // 196 scan blocks

    // ---- preprocessing: degrees, norms, CSR (multi-block scan), fp16 weights
    cudaMemsetAsync(ideg, 0, NN * sizeof(int));
    cudaMemsetAsync(odeg, 0, NN * sizeof(int));
    cudaMemsetAsync(cnt,  0, NN * sizeof(int));
    deg_k<<<cdiv(NE, TB), TB>>>(src, dst);
    norm_k<<<cdiv(NN, TB), TB>>>();
    bscan_k<<<NB, 256>>>();
    bsum_k<<<1, 256>>>();
    badd_k<<<NB, 256>>>();
    fill_k<<<cdiv(NE, TB), TB>>>(src, dst, efet);
    wcvt_k<256, 128><<<cdiv(256 * 128, TB), TB>>>(W2, w2t);
    wcvt_k<128, 64><<<cdiv(128 * 64, TB), TB>>>(W3, w3t);
    wcvt_k<64, 32><<<cdiv(64 * 32, TB), TB>>>(W4, w4t);

    // ---- gc1 fused: g1 = relu((agg16(x*no) @ W1)*ni + b1) -> fp16
    g1_k<<<cdiv(NN, 64), TB>>>(x, W1, b1, hB);                                // g1: hB

    // ---- y1 = g1 @ W2 (mma 256->128) BEFORE ewa1 (commuted)
    mma_gemm_k<256, 128><<<cdiv(NN, 64), TB>>>(hB, w2t, hA);                  // y1: hA
    // ---- ewa1 at width 128: m2 = ewa(y1) * out_norm (relu is identity)
    gather_h_k<128, 1, false, false, true, true><<<cdiv(NN, 16), TB>>>(hA, nullptr, hC);
    // ---- gc2 aggregation: g2 = relu(agg(m2)*ni + b2)
    gather_h_k<128, 0, true, true, false, true><<<cdiv(NN, 16), TB>>>(hC, b2, hB); // g2: hB

    // ---- y2 = g2 @ W3 (mma 128->64) BEFORE ewa2
    mma_gemm_k<128, 64><<<cdiv(NN, 128), TB>>>(hB, w3t, hA);                  // y2: hA
    // ---- ewa2 at width 64
    gather_h_k<64, 1, false, false, true, true><<<cdiv(NN, 32), TB>>>(hA, nullptr, hC);
    // ---- gc3 aggregation: g3 = relu(agg(m3)*ni + b3)
    gather_h_k<64, 0, true, true, false, true><<<cdiv(NN, 32), TB>>>(hC, b3, hB);  // g3: hB

    // ---- y3 = g3 @ W4 (mma 64->32) BEFORE ewa3
    mma_gemm_k<64, 32><<<cdiv(NN, 128), TB>>>(hB, w4t, hA);                   // y3: hA
    // ---- ewa3 at width 32
    gather_h_k<32, 1, false, false, true, true><<<cdiv(NN, 64), TB>>>(hA, nullptr, hC);

    // ---- gc4-agg + gemm5 fused: m5 = (relu(agg(m4)*ni+b4)*no) @ W5
    g45_k<<<cdiv(NN, 64), TB>>>(hC, b4, W5, bufB);                            // m5: bufB

    // ---- gc5 aggregation: out = agg(m5)*ni + b5
    gather_k<4, 0, true, false><<<cdiv(NN, 256), TB>>>(bufB, b5, out);
}

// round 15
// speedup vs baseline: 1.3810x; 1.0356x over previous
#include <cuda_runtime.h>
#include <cuda_fp16.h>
#include <cuda_bf16.h>
#include <cstddef>
#include <cstdint>

// ---------------------------------------------------------------------------
// GCN: 5 GraphConv + 3 edge-weighted aggregations. CSR-gather + tensor cores.
// R15 = R14 (250.2us) with preprocessing launch-count surgery ONLY:
//   - one memset over merged [ideg|odeg|cnt] counter block (-2 launches)
//   - norms folded into multi-block bscan (coalesced, parallel)  (-1 launch)
//   - bsum eliminated: badd blocks redundantly scan 196 block sums (-1 launch)
//   - single wcvt kernel for all three weight transposes           (-2 launches)
// Tiny single-block kernels cost ~4us each (measured bsum_k=3.97us);
// the R8 trap (single-block strided scan) is NOT reintroduced.
// Hot-path kernels byte-frozen from R14.
// ---------------------------------------------------------------------------

#define NN 50000
#define NE 800000
#define NB_SCAN ((NN + 255) / 256)

__device__ int   g_cnt3[3 * NN];           // [ideg | odeg | fill-cursor]
__device__ int   g_off[NN + 1];
__device__ int   g_bsum[256];
__device__ __align__(16) int2  g_edge[NE]; // {src, __float_as_int(efet)}
__device__ float g_norm_out[NN];
__device__ float g_norm_in[NN];
__device__ __align__(16) float g_bufA[(size_t)NN * 256];
__device__ __align__(16) float g_bufB[(size_t)NN * 256];
__device__ __align__(16) float g_bufC[(size_t)NN * 256];
// transposed fp16 weights: W2t[128][256], W3t[64][128], W4t[32][64]
__device__ __align__(16) __half g_w2t[128 * 256];
__device__ __align__(16) __half g_w3t[64 * 128];
__device__ __align__(16) __half g_w4t[32 * 64];

// ---- degrees ---------------------------------------------------------------

__global__ void deg_k(const int* __restrict__ src, const int* __restrict__ dst) {
    int e = blockIdx.x * blockDim.x + threadIdx.x;
    if (e < NE) {
        atomicAdd(&g_cnt3[NN + src[e]], 1);   // odeg
        atomicAdd(&g_cnt3[dst[e]], 1);        // ideg
    }
}

// ---- multi-block scan phase 1 + norms (coalesced, parallel) ----------------

__global__ void bscan_k() {
    __shared__ int sh[256];
    int t = threadIdx.x;
    int i = blockIdx.x * 256 + t;
    int id = (i < NN) ? g_cnt3[i] : 0;
    sh[t] = id;
    __syncthreads();
    for (int o = 1; o < 256; o <<= 1) {
        int u = (t >= o) ? sh[t - o] : 0;
        __syncthreads();
        sh[t] += u;
        __syncthreads();
    }
    if (i < NN) {
        g_off[i] = sh[t] - id;                 // local exclusive
        g_norm_in[i]  = rsqrtf(fmaxf((float)id, 1.0f));
        g_norm_out[i] = rsqrtf(fmaxf((float)g_cnt3[NN + i], 1.0f));
    }
    if (t == 255) g_bsum[blockIdx.x] = sh[255];
}

// ---- phase 2: each block redundantly scans the block sums, adds its offset -

__global__ void badd_k() {
    __shared__ int sh[256];
    int t = threadIdx.x;
    sh[t] = (t < NB_SCAN) ? g_bsum[t] : 0;
    __syncthreads();
    for (int o = 1; o < 256; o <<= 1) {
        int u = (t >= o) ? sh[t - o] : 0;
        __syncthreads();
        sh[t] += u;
        __syncthreads();
    }
    // exclusive offset for this block = inclusive sum up to blockIdx-1
    int boff = (blockIdx.x == 0) ? 0 : sh[blockIdx.x - 1];
    int i = blockIdx.x * 256 + t;
    if (i < NN) g_off[i] += boff;
    if (blockIdx.x == 0 && t == 0) g_off[NN] = NE;
}

__global__ void fill_k(const int* __restrict__ src, const int* __restrict__ dst,
                       const float* __restrict__ efet) {
    int e = blockIdx.x * blockDim.x + threadIdx.x;
    if (e < NE) {
        int d = dst[e];
        int pos = g_off[d] + atomicAdd(&g_cnt3[2 * NN + d], 1);
        g_edge[pos] = make_int2(src[e], __float_as_int(efet[e]));
    }
}

// ---- all W -> Wt fp16 transposes in one kernel -----------------------------

__global__ void wcvt_all_k(const float* __restrict__ W2,
                           const float* __restrict__ W3,
                           const float* __restrict__ W4) {
    int i = blockIdx.x * blockDim.x + threadIdx.x;
    if (i < 256 * 128) {
        int k = i / 128, n = i % 128;
        g_w2t[(size_t)n * 256 + k] = __float2half(W2[i]);
    } else if (i < 256 * 128 + 128 * 64) {
        int j = i - 256 * 128;
        int k = j / 64, n = j % 64;
        g_w3t[(size_t)n * 128 + k] = __float2half(W3[j]);
    } else if (i < 256 * 128 + 128 * 64 + 64 * 32) {
        int j = i - 256 * 128 - 128 * 64;
        int k = j / 32, n = j % 32;
        g_w4t[(size_t)n * 64 + k] = __float2half(W4[j]);
    }
}

// ---- fp32 gather (final 4-wide) --------------------------------------------
// WMODE: 0 = w=1, 1 = w=efet, 2 = w=out_norm[src]

template <int F, int WMODE, bool EPI, bool RELU>
__global__ void gather_k(const float* __restrict__ m,
                         const float* __restrict__ b,
                         float* __restrict__ out) {
    constexpr int NT = F / 4;
    constexpr int NPB = 256 / NT;
    int t = threadIdx.x;
    int node = blockIdx.x * NPB + t / NT;
    int c = t % NT;
    if (node >= NN) return;
    int beg = g_off[node], end = g_off[node + 1];

    float4 acc = make_float4(0.f, 0.f, 0.f, 0.f);
    for (int e = beg; e < end; e++) {
        int2 sc = g_edge[e];
        int s = sc.x;
        float w = 1.0f;
        if (WMODE == 1) w = __int_as_float(sc.y);
        if (WMODE == 2) w = g_norm_out[s];
        float4 v = *(const float4*)(m + (size_t)s * F + c * 4);
        acc.x += v.x * w; acc.y += v.y * w; acc.z += v.z * w; acc.w += v.w * w;
    }
    if (EPI) {
        float ni = g_norm_in[node];
        acc.x = acc.x * ni + b[c * 4 + 0];
        acc.y = acc.y * ni + b[c * 4 + 1];
        acc.z = acc.z * ni + b[c * 4 + 2];
        acc.w = acc.w * ni + b[c * 4 + 3];
    }
    if (RELU) {
        acc.x = fmaxf(acc.x, 0.f); acc.y = fmaxf(acc.y, 0.f);
        acc.z = fmaxf(acc.z, 0.f); acc.w = fmaxf(acc.w, 0.f);
    }
    *(float4*)(out + (size_t)node * F + c * 4) = acc;
}

// ---- fp16-input gather ------------------------------------------------------
// 8 halves per thread, fp32 accumulation, x2 edge unroll (frozen config).
// ONORM: multiply final result by out_norm[node].  OH: fp16 output.

__device__ __forceinline__ void acc8(float* a, uint4 r, float w) {
    float2 f;
    f = __half22float2(*(const __half2*)&r.x); a[0] += f.x * w; a[1] += f.y * w;
    f = __half22float2(*(const __half2*)&r.y); a[2] += f.x * w; a[3] += f.y * w;
    f = __half22float2(*(const __half2*)&r.z); a[4] += f.x * w; a[5] += f.y * w;
    f = __half22float2(*(const __half2*)&r.w); a[6] += f.x * w; a[7] += f.y * w;
}

template <int F, int WMODE, bool EPI, bool RELU, bool ONORM, bool OH>
__global__ void gather_h_k(const __half* __restrict__ m,
                           const float* __restrict__ b,
                           void* __restrict__ outp) {
    constexpr int NT = F / 8;
    constexpr int NPB = 256 / NT;
    int t = threadIdx.x;
    int node = blockIdx.x * NPB + t / NT;
    int c = t % NT;
    if (node >= NN) return;
    int beg = g_off[node], end = g_off[node + 1];

    float acc[8];
#pragma unroll
    for (int i = 0; i < 8; i++) acc[i] = 0.f;

    const uint4* base = (const uint4*)m;
    int e = beg;
    for (; e + 2 <= end; e += 2) {
        int2 sc0 = g_edge[e], sc1 = g_edge[e + 1];
        float w0 = 1.f, w1 = 1.f;
        if (WMODE == 1) { w0 = __int_as_float(sc0.y); w1 = __int_as_float(sc1.y); }
        uint4 r0 = base[(size_t)sc0.x * NT + c];
        uint4 r1 = base[(size_t)sc1.x * NT + c];
        acc8(acc, r0, w0);
        acc8(acc, r1, w1);
    }
    if (e < end) {
        int2 sc = g_edge[e];
        float w = (WMODE == 1) ? __int_as_float(sc.y) : 1.f;
        uint4 r = base[(size_t)sc.x * NT + c];
        acc8(acc, r, w);
    }

    if (EPI) {
        float ni = g_norm_in[node];
#pragma unroll
        for (int i = 0; i < 8; i++) acc[i] = acc[i] * ni + b[c * 8 + i];
    }
    if (RELU) {
#pragma unroll
        for (int i = 0; i < 8; i++) acc[i] = fmaxf(acc[i], 0.f);
    }
    if (ONORM) {
        float no = g_norm_out[node];
#pragma unroll
        for (int i = 0; i < 8; i++) acc[i] *= no;
    }
    if (OH) {
        __half2 h0 = __floats2half2_rn(acc[0], acc[1]);
        __half2 h1 = __floats2half2_rn(acc[2], acc[3]);
        __half2 h2 = __floats2half2_rn(acc[4], acc[5]);
        __half2 h3 = __floats2half2_rn(acc[6], acc[7]);
        uint4 r;
        r.x = *(const unsigned*)&h0; r.y = *(const unsigned*)&h1;
        r.z = *(const unsigned*)&h2; r.w = *(const unsigned*)&h3;
        ((uint4*)outp)[(size_t)node * NT + c] = r;
    } else {
        float* o = (float*)outp + (size_t)node * F + c * 8;
        *(float4*)(o + 0) = make_float4(acc[0], acc[1], acc[2], acc[3]);
        *(float4*)(o + 4) = make_float4(acc[4], acc[5], acc[6], acc[7]);
    }
}

// ---- tensor-core GEMM: D[M,N] = A[M,K] @ W[K,N], fp16 in / fp32 acc --------

template <int K, int N>
__global__ void mma_gemm_k(const __half* __restrict__ A,
                           const __half* __restrict__ Wt,
                           __half* __restrict__ D) {
    constexpr int WN = (N >= 64) ? 64 : N;       // warp n-extent
    constexpr int TN = WN / 8;                   // n8 tiles per warp
    constexpr int WARPS_N = N / WN;
    constexpr int WARPS_M = 8 / WARPS_N;
    constexpr int BM = WARPS_M * 16;
    constexpr int PITCH = K + 8;                 // +16B pad -> bank rotation
    constexpr int KC = K / 16;                   // k16 chunks

    __shared__ __half sA[BM * PITCH];

    const int tid = threadIdx.x;
    const int lane = tid & 31;
    const int wid = tid >> 5;
    const int wm = wid % WARPS_M;
    const int wn = wid / WARPS_M;
    const int blockStart = blockIdx.x * BM;

    for (int i = tid; i < BM * (K / 8); i += 256) {
        int row = i / (K / 8), chunk = i % (K / 8);
        int node = blockStart + row;
        uint4 v = make_uint4(0, 0, 0, 0);
        if (node < NN) v = ((const uint4*)A)[(size_t)node * (K / 8) + chunk];
        *(uint4*)(&sA[row * PITCH + chunk * 8]) = v;
    }
    __syncthreads();

    float acc[TN][4];
#pragma unroll
    for (int t = 0; t < TN; t++)
#pragma unroll
        for (int i = 0; i < 4; i++) acc[t][i] = 0.f;

    const int q = lane >> 3, r = lane & 7;
    const int arow = wm * 16 + r + 8 * (q & 1);
    const int acol0 = 8 * (q >> 1);
    unsigned abase;
    {
        const void* p = &sA[arow * PITCH + acol0];
        asm("{ .reg .u64 t; cvta.to.shared.u64 t, %1; cvt.u32.u64 %0, t; }"
            : "=r"(abase) : "l"(p));
    }

    const __half* wbase = Wt + (size_t)(wn * WN + (lane >> 2)) * K + (lane & 3) * 2;

#pragma unroll
    for (int kc = 0; kc < KC; kc++) {
        unsigned a0, a1, a2, a3;
        asm volatile("ldmatrix.sync.aligned.m8n8.x4.shared.b16 {%0,%1,%2,%3}, [%4];"
                     : "=r"(a0), "=r"(a1), "=r"(a2), "=r"(a3)
                     : "r"(abase + kc * 32));
#pragma unroll
        for (int tn = 0; tn < TN; tn++) {
            unsigned b0 = *(const unsigned*)(wbase + (size_t)tn * 8 * K + kc * 16);
            unsigned b1 = *(const unsigned*)(wbase + (size_t)tn * 8 * K + kc * 16 + 8);
            asm volatile(
                "mma.sync.aligned.m16n8k16.row.col.f32.f16.f16.f32 "
                "{%0,%1,%2,%3}, {%4,%5,%6,%7}, {%8,%9}, {%0,%1,%2,%3};"
                : "+f"(acc[tn][0]), "+f"(acc[tn][1]), "+f"(acc[tn][2]), "+f"(acc[tn][3])
                : "r"(a0), "r"(a1), "r"(a2), "r"(a3), "r"(b0), "r"(b1));
        }
    }

    const int node0 = blockStart + wm * 16 + (lane >> 2);
    const int node1 = node0 + 8;
#pragma unroll
    for (int tn = 0; tn < TN; tn++) {
        int gcol = wn * WN + tn * 8 + (lane & 3) * 2;
        if (node0 < NN) {
            __half2 h = __floats2half2_rn(acc[tn][0], acc[tn][1]);
            *(unsigned*)(D + (size_t)node0 * N + gcol) = *(const unsigned*)&h;
        }
        if (node1 < NN) {
            __half2 h = __floats2half2_rn(acc[tn][2], acc[tn][3]);
            *(unsigned*)(D + (size_t)node1 * N + gcol) = *(const unsigned*)&h;
        }
    }
}

// ---- fused gc1: gather 16-wide scaled x + (agg @ W1)*in_norm+b1, relu ------

__global__ void g1_k(const float* __restrict__ x, const float* __restrict__ W1,
                     const float* __restrict__ b1, __half* __restrict__ out) {
    __shared__ float sX[64 * 16];
    const int tid = threadIdx.x;
    const int nbase = blockIdx.x * 64;

    {
        int g = tid / 4, c = tid % 4;
        int node = nbase + g;
        float4 a = make_float4(0.f, 0.f, 0.f, 0.f);
        if (node < NN) {
            int beg = g_off[node], end = g_off[node + 1];
            for (int e = beg; e < end; e++) {
                int s = g_edge[e].x;
                float w = g_norm_out[s];
                float4 v = *(const float4*)(x + (size_t)s * 16 + c * 4);
                a.x += v.x * w; a.y += v.y * w; a.z += v.z * w; a.w += v.w * w;
            }
        }
        *(float4*)(&sX[g * 16 + c * 4]) = a;
    }
    __syncthreads();

    const int j = tid;
    float w[16];
#pragma unroll
    for (int k = 0; k < 16; k++) w[k] = W1[k * 256 + j];
    float bj = b1[j];
#pragma unroll 4
    for (int ln = 0; ln < 64; ln++) {
        int node = nbase + ln;
        if (node >= NN) break;
        float acc = 0.f;
#pragma unroll
        for (int k = 0; k < 16; k++) acc += sX[ln * 16 + k] * w[k];
        acc = acc * g_norm_in[node] + bj;
        out[(size_t)node * 256 + j] = __float2half(fmaxf(acc, 0.f));
    }
}

// ---- fused gc4-agg + gemm5: h4 = relu(agg(m4)*ni+b4); m5 = (h4*no)@W5 ------

__global__ void g45_k(const __half* __restrict__ m4, const float* __restrict__ b4,
                      const float* __restrict__ W5, float* __restrict__ m5) {
    __shared__ float sH[64 * 32];
    __shared__ float sW[32 * 4];
    const int tid = threadIdx.x;
    if (tid < 128) sW[tid] = W5[tid];
    const int g = tid / 4, c = tid % 4;     // 64 nodes x 4 threads
    const int node = blockIdx.x * 64 + g;

    float acc[8];
#pragma unroll
    for (int i = 0; i < 8; i++) acc[i] = 0.f;
    if (node < NN) {
        int beg = g_off[node], end = g_off[node + 1];
        const uint4* base = (const uint4*)m4;     // row stride = 4 uint4s
        int e = beg;
        for (; e + 2 <= end; e += 2) {
            int2 sc0 = g_edge[e], sc1 = g_edge[e + 1];
            uint4 r0 = base[(size_t)sc0.x * 4 + c];
            uint4 r1 = base[(size_t)sc1.x * 4 + c];
            acc8(acc, r0, 1.f);
            acc8(acc, r1, 1.f);
        }
        if (e < end) {
            int2 sc = g_edge[e];
            uint4 r = base[(size_t)sc.x * 4 + c];
            acc8(acc, r, 1.f);
        }
        float ni = g_norm_in[node];
        float no = g_norm_out[node];
#pragma unroll
        for (int i = 0; i < 8; i++)
            acc[i] = fmaxf(acc[i] * ni + b4[c * 8 + i], 0.f) * no;
    }
#pragma unroll
    for (int i = 0; i < 8; i++) sH[g * 32 + c * 8 + i] = acc[i];
    __syncthreads();

    if (node >= NN) return;
    float o = 0.f;
#pragma unroll
    for (int k = 0; k < 32; k++) o += sH[g * 32 + k] * sW[k * 4 + c];
    m5[(size_t)node * 4 + c] = o;
}

// ---------------------------------------------------------------------------

static inline int cdiv(long long a, int b) { return (int)((a + b - 1) / b); }

extern "C" void kernel_launch(void* const* d_in, const int* in_sizes, int n_in,
                              void* d_out, int out_size) {
    (void)in_sizes; (void)n_in; (void)out_size;
    const float* x    = (const float*)d_in[0];
    const float* efet = (const float*)d_in[1];
    const int*   src  = (const int*)d_in[2];
    const int*   dst  = (const int*)d_in[3];
    const float* W1 = (const float*)d_in[4];  const float* b1 = (const float*)d_in[5];
    const float* W2 = (const float*)d_in[6];  const float* b2 = (const float*)d_in[7];
    const float* W3 = (const float*)d_in[8];  const float* b3 = (const float*)d_in[9];
    const float* W4 = (const float*)d_in[10]; const float* b4 = (const float*)d_in[11];
    const float* W5 = (const float*)d_in[12]; const float* b5 = (const float*)d_in[13];
    float* out = (float*)d_out;

    float *bufA, *bufB, *bufC;
    int *cnt3;
    __half *w2t, *w3t, *w4t;
    cudaGetSymbolAddress((void**)&bufA, g_bufA);
    cudaGetSymbolAddress((void**)&bufB, g_bufB);
    cudaGetSymbolAddress((void**)&bufC, g_bufC);
    cudaGetSymbolAddress((void**)&cnt3, g_cnt3);
    cudaGetSymbolAddress((void**)&w2t, g_w2t);
    cudaGetSymbolAddress((void**)&w3t, g_w3t);
    cudaGetSymbolAddress((void**)&w4t, g_w4t);
    __half* hA = (__half*)bufA;
    __half* hB = (__half*)bufB;
    __half* hC = (__half*)bufC;

    const int TB = 256;

    // ---- preprocessing (consolidated; multi-block scan kept from R14)
    cudaMemsetAsync(cnt3, 0, 3 * NN * sizeof(int));
    deg_k<<<cdiv(NE, TB), TB>>>(src, dst);
    bscan_k<<<NB_SCAN, 256>>>();
    badd_k<<<NB_SCAN, 256>>>();
    fill_k<<<cdiv(NE, TB), TB>>>(src, dst, efet);
    wcvt_all_k<<<cdiv(256 * 128 + 128 * 64 + 64 * 32, TB), TB>>>(W2, W3, W4);

    // ---- gc1 fused: g1 = relu((agg16(x*no) @ W1)*ni + b1) -> fp16
    g1_k<<<cdiv(NN, 64), TB>>>(x, W1, b1, hB);                                // g1: hB

    // ---- y1 = g1 @ W2 (mma 256->128) BEFORE ewa1 (commuted)
    mma_gemm_k<256, 128><<<cdiv(NN, 64), TB>>>(hB, w2t, hA);                  // y1: hA
    // ---- ewa1 at width 128: m2 = ewa(y1) * out_norm (relu is identity)
    gather_h_k<128, 1, false, false, true, true><<<cdiv(NN, 16), TB>>>(hA, nullptr, hC);
    // ---- gc2 aggregation: g2 = relu(agg(m2)*ni + b2)
    gather_h_k<128, 0, true, true, false, true><<<cdiv(NN, 16), TB>>>(hC, b2, hB); // g2: hB

    // ---- y2 = g2 @ W3 (mma 128->64) BEFORE ewa2
    mma_gemm_k<128, 64><<<cdiv(NN, 128), TB>>>(hB, w3t, hA);                  // y2: hA
    // ---- ewa2 at width 64
    gather_h_k<64, 1, false, false, true, true><<<cdiv(NN, 32), TB>>>(hA, nullptr, hC);
    // ---- gc3 aggregation: g3 = relu(agg(m3)*ni + b3)
    gather_h_k<64, 0, true, true, false, true><<<cdiv(NN, 32), TB>>>(hC, b3, hB);  // g3: hB

    // ---- y3 = g3 @ W4 (mma 64->32) BEFORE ewa3
    mma_gemm_k<64, 32><<<cdiv(NN, 128), TB>>>(hB, w4t, hA);                   // y3: hA
    // ---- ewa3 at width 32
    gather_h_k<32, 1, false, false, true, true><<<cdiv(NN, 64), TB>>>(hA, nullptr, hC);

    // ---- gc4-agg + gemm5 fused: m5 = (relu(agg(m4)*ni+b4)*no) @ W5
    g45_k<<<cdiv(NN, 64), TB>>>(hC, b4, W5, bufB);                            // m5: bufB

    // ---- gc5 aggregation: out = agg(m5)*ni + b5
    gather_k<4, 0, true, false><<<cdiv(NN, 256), TB>>>(bufB, b5, out);
}